// round 12
// baseline (speedup 1.0000x reference)
#include <cuda_runtime.h>

#define HIDDEN 32
#define FF 40
#define TSTEPS 512
#define BATCH 16384
#define EPB 128           /* elements per block; each thread handles 2 */
#define THREADS 512       /* 16 warps = 8 column-slices x 2 element-groups */

typedef unsigned long long u64;

__device__ __forceinline__ u64 pk(float a, float b) {
    u64 r; asm("mov.b64 %0,{%1,%2};" : "=l"(r) : "f"(a), "f"(b)); return r;
}
__device__ __forceinline__ void upk(u64 v, float& a, float& b) {
    asm("mov.b64 {%0,%1},%2;" : "=f"(a), "=f"(b) : "l"(v));
}
__device__ __forceinline__ u64 f2fma(u64 a, u64 b, u64 c) {
    u64 d; asm("fma.rn.f32x2 %0,%1,%2,%3;" : "=l"(d) : "l"(a), "l"(b), "l"(c)); return d;
}
// sigmoid via ex2/rcp approx (~1e-6 rel; proven across rounds)
__device__ __forceinline__ float sigm(float x) {
    float e, r;
    asm("ex2.approx.ftz.f32 %0,%1;" : "=f"(e) : "f"(x * -1.4426950408889634f));
    asm("rcp.approx.ftz.f32 %0,%1;" : "=f"(r) : "f"(1.0f + e));
    return r;
}

// Dynamic smem layout (bytes; every u64 region 8B-aligned)
#define OFF_WF   0            /* fused Wf[40][80] f32 = 12800           */
#define OFF_U    12800        /* u-row  [80] f32                        */
#define OFF_BF   13120        /* fused bias (recurrent) [80]            */
#define OFF_B0   13440        /* plain layer-1 bias (t=0) [80]          */
#define OFF_W2HO 13760        /* W2ho [40]                              */
#define OFF_SBUF 13920        /* u64[2][20*EPB] = 40960                 */
#define OFF_OBUF 54880        /* f32[2][4*EPB]  = 4096                  */
#define SMEM_TOTAL 58976

__global__ void __launch_bounds__(THREADS, 1) rnn_fused16_kernel(
    const float* __restrict__ inp,
    const float* __restrict__ W1hh, const float* __restrict__ b1hh,
    const float* __restrict__ W2hh, const float* __restrict__ b2hh,
    const float* __restrict__ W1ho, const float* __restrict__ b1ho,
    const float* __restrict__ W2ho, const float* __restrict__ b2ho,
    float* __restrict__ out)
{
    extern __shared__ __align__(16) char smem[];
    float* sWf   = (float*)(smem + OFF_WF);    // [k<40][j<80]; j<40 hh, j>=40 ho
    float* sU    = (float*)(smem + OFF_U);
    float* sBf   = (float*)(smem + OFF_BF);
    float* sB0   = (float*)(smem + OFF_B0);
    float* sW2ho = (float*)(smem + OFF_W2HO);
    u64*   sbuf  = (u64*)  (smem + OFF_SBUF);  // s = sigmoid(z_hh), 20 pairs, x2 parity
    float* obuf  = (float*)(smem + OFF_OBUF);  // 4 output partials, x2 parity

    const int tid = threadIdx.x;

    // ---- init: fused weights Wf[k][j] = sum_i W2hh[k][i] * W1x[i][jcol] ----
    for (int idx = tid; idx < 40 * 80; idx += THREADS) {
        int k = idx / 80, j = idx % 80;
        const float* W1p = (j < 40) ? (W1hh + j) : (W1ho + (j - 40));  // stride FF over i
        const float* W2p = W2hh + k * HIDDEN;
        float acc = 0.0f;
        #pragma unroll
        for (int i = 0; i < HIDDEN; i++) acc += W2p[i] * W1p[i * FF];
        sWf[idx] = acc;
    }
    for (int j = tid; j < 80; j += THREADS) {
        const float* W1p = (j < 40) ? (W1hh + j) : (W1ho + (j - 40));
        float b1 = (j < 40) ? b1hh[j] : b1ho[j - 40];
        float acc = 0.0f;
        #pragma unroll
        for (int i = 0; i < HIDDEN; i++) acc += b2hh[i] * W1p[i * FF];
        sB0[j] = b1;              // t=0: h0 = 0 exactly -> plain layer-1 bias
        sBf[j] = b1 + acc;        // t>0: bias absorbs b2hh @ W1[0:32]
        sU[j]  = W1p[32 * FF];    // input row W1[32][jcol]
    }
    for (int j = tid; j < FF; j += THREADS) sW2ho[j] = W2ho[j];
    const float bias_o = b2ho[0];
    __syncthreads();

    const int lane = tid & 31;
    const int wid  = tid >> 5;          // 0..15
    const int cg   = wid & 7;           // column slice: j-pairs [5cg, 5cg+5)
    const int eg   = wid >> 3;          // element group: slots [64eg, 64eg+64)
    const bool is_hh = (cg < 4);        // cols 0..39 -> s state; 40..79 -> output head
    const int JB = 5 * cg;
    const int e0i = eg * 64 + lane;     // in-block element slots
    const int e1i = e0i + 32;

    const size_t ebase = (size_t)blockIdx.x * EPB;
    const float* __restrict__ ip0 = inp + (ebase + e0i) * TSTEPS;
    const float* __restrict__ ip1 = inp + (ebase + e1i) * TSTEPS;
    float* __restrict__ op0 = out + (ebase + e0i) * TSTEPS;
    float* __restrict__ op1 = out + (ebase + e1i) * TSTEPS;

    const u64* U64  = (const u64*)sU  + JB;
    const u64* Bf64 = (const u64*)sBf + JB;
    const u64* Wo64 = (const u64*)sW2ho + (JB - 20);   // valid for ho warps only
    const bool is_comb = (cg == 0);                    // per-egroup output combiner

    // ---- t = 0: z = u0 * Urow + B0 (h0 = 0) ----
    u64 z0[5], z1[5];
    {
        const u64* B0p = (const u64*)sB0 + JB;
        float u0 = ip0[0], u1 = ip1[0];
        u64 cu0 = pk(u0, u0), cu1 = pk(u1, u1);
        #pragma unroll
        for (int q = 0; q < 5; q++) {
            u64 Uq = U64[q], Bq = B0p[q];
            z0[q] = f2fma(cu0, Uq, Bq);
            z1[q] = f2fma(cu1, Uq, Bq);
        }
    }

    #pragma unroll 1
    for (int t = 0; t < TSTEPS; t++) {
        const int par = t & 1;
        float u0n = ip0[(t + 1) & (TSTEPS - 1)];
        float u1n = ip1[(t + 1) & (TSTEPS - 1)];

        // ===== phase 1: consume z[t] =====
        if (is_hh) {
            // s = sigmoid(z_hh) -> sbuf[par], pairs [JB, JB+5)
            u64* sb = sbuf + par * (20 * EPB);
            #pragma unroll
            for (int q = 0; q < 5; q++) {
                float a, b; upk(z0[q], a, b);
                sb[(JB + q) * EPB + e0i] = pk(sigm(a), sigm(b));
                float c, d; upk(z1[q], c, d);
                sb[(JB + q) * EPB + e1i] = pk(sigm(c), sigm(d));
            }
        } else {
            // partial out dot: sigmoid(z_ho) . W2ho[slice] -> obuf[par][cg-4]
            u64 acc0 = 0ull, acc1 = 0ull;
            #pragma unroll
            for (int q = 0; q < 5; q++) {
                u64 W = Wo64[q];
                float a, b; upk(z0[q], a, b);
                acc0 = f2fma(pk(sigm(a), sigm(b)), W, acc0);
                float c, d; upk(z1[q], c, d);
                acc1 = f2fma(pk(sigm(c), sigm(d)), W, acc1);
            }
            float* ob = obuf + par * (4 * EPB) + (cg - 4) * EPB;
            float a, b; upk(acc0, a, b); ob[e0i] = a + b;
            float c, d; upk(acc1, c, d); ob[e1i] = c + d;
        }

        __syncthreads();   // s + output partials published

        // cg==0 warp of each element group combines partials and writes out[t]
        if (is_comb) {
            const float* ob = obuf + par * (4 * EPB);
            op0[t] = ob[e0i] + ob[EPB + e0i] + ob[2 * EPB + e0i] + ob[3 * EPB + e0i]
                   + bias_o;
            op1[t] = ob[e1i] + ob[EPB + e1i] + ob[2 * EPB + e1i] + ob[3 * EPB + e1i]
                   + bias_o;
        }

        // ===== phase 2: GEMV -> z[t+1] = s @ Wf + u_{t+1}*U + Bf =====
        {
            u64 cu0 = pk(u0n, u0n), cu1 = pk(u1n, u1n);
            #pragma unroll
            for (int q = 0; q < 5; q++) {
                u64 Uq = U64[q], Bq = Bf64[q];
                z0[q] = f2fma(cu0, Uq, Bq);
                z1[q] = f2fma(cu1, Uq, Bq);
            }
        }
        {
            const u64* sb = sbuf + par * (20 * EPB);
            #pragma unroll 4
            for (int kp = 0; kp < 20; kp++) {
                float sa0, sa1; upk(sb[kp * EPB + e0i], sa0, sa1);
                float sbv0, sbv1; upk(sb[kp * EPB + e1i], sbv0, sbv1);
                u64 pa0 = pk(sa0, sa0), pb0 = pk(sbv0, sbv0);
                const u64* w0 = (const u64*)(sWf + (2 * kp) * 80) + JB;
                #pragma unroll
                for (int q = 0; q < 5; q++) {
                    u64 W = w0[q];
                    z0[q] = f2fma(pa0, W, z0[q]);
                    z1[q] = f2fma(pb0, W, z1[q]);
                }
                u64 pa1 = pk(sa1, sa1), pb1 = pk(sbv1, sbv1);
                const u64* w1 = (const u64*)(sWf + (2 * kp + 1) * 80) + JB;
                #pragma unroll
                for (int q = 0; q < 5; q++) {
                    u64 W = w1[q];
                    z0[q] = f2fma(pa1, W, z0[q]);
                    z1[q] = f2fma(pb1, W, z1[q]);
                }
            }
        }
        // single barrier per step: next iteration writes the OTHER parity of
        // sbuf/obuf, and skew across one barrier is at most one phase -> safe.
    }
}

extern "C" void kernel_launch(void* const* d_in, const int* in_sizes, int n_in,
                              void* d_out, int out_size) {
    const float* inp  = (const float*)d_in[0];
    const float* W1hh = (const float*)d_in[1];
    const float* b1hh = (const float*)d_in[2];
    const float* W2hh = (const float*)d_in[3];
    const float* b2hh = (const float*)d_in[4];
    const float* W1ho = (const float*)d_in[5];
    const float* b1ho = (const float*)d_in[6];
    const float* W2ho = (const float*)d_in[7];
    const float* b2ho = (const float*)d_in[8];
    float* out = (float*)d_out;

    // Idempotent, capture-safe.
    cudaFuncSetAttribute(rnn_fused16_kernel,
                         cudaFuncAttributeMaxDynamicSharedMemorySize, SMEM_TOTAL);

    dim3 grid(BATCH / EPB);   // 128 blocks x 512 threads: 16 warps/SM, 4/SMSP
    dim3 block(THREADS);
    rnn_fused16_kernel<<<grid, block, SMEM_TOTAL>>>(inp, W1hh, b1hh, W2hh, b2hh,
                                                    W1ho, b1ho, W2ho, b2ho, out);
}